// round 5
// baseline (speedup 1.0000x reference)
#include <cuda_runtime.h>
#include <cuda_bf16.h>
#include <cstdint>
#include <math.h>

typedef unsigned long long ull;

// ---------------- problem dims ----------------
#define NE     16384
#define CD     256
#define HW     1024
#define NTOK   4096
#define ZQ_N   (NTOK * CD)
#define NCUTS  32
#define EMB    512
#define BATCH  4

// ---------------- GEMM tiling ----------------
// CTA: 128 tokens x 512 codes; 8 warps of 64x64; A resident; B streamed
// as 256-code x 64-k slices, double buffered. 1 CTA/SM (smem 141KB, ~220 regs).
#define AROW    528                   // 512B data + 16B pad
#define APLANE  (128 * AROW)          // 67584
#define BROW    144                   // 128B data + 16B pad
#define BTILE   (256 * BROW)          // 36864
#define SMEM_B  (APLANE + 2 * BTILE)  // 141312

// ---------------- device globals ----------------
__device__ __align__(16) __nv_bfloat16 g_Ah[NTOK * CD];
__device__ __align__(16) __nv_bfloat16 g_Bh[NE * CD];
__device__ float g_hn[NE];
__device__ ull   g_top[(size_t)NTOK * 256];   // 8 keys per (token, ngrp)
__device__ int   g_best[NTOK];

// ---------------- asm helpers ----------------
static __device__ __forceinline__ uint32_t smem_u32(const void* p) {
    uint32_t a;
    asm("{ .reg .u64 t; cvta.to.shared.u64 t, %1; cvt.u32.u64 %0, t; }" : "=r"(a) : "l"(p));
    return a;
}
static __device__ __forceinline__ void cp16(uint32_t dst, const void* src) {
    asm volatile("cp.async.cg.shared.global [%0], [%1], 16;" :: "r"(dst), "l"(src));
}
static __device__ __forceinline__ void cp_commit() {
    asm volatile("cp.async.commit_group;");
}
template <int N> static __device__ __forceinline__ void cp_wait() {
    asm volatile("cp.async.wait_group %0;" :: "n"(N));
}
#define LDSM4(r, addr) \
    asm volatile("ldmatrix.sync.aligned.m8n8.x4.shared.b16 {%0,%1,%2,%3}, [%4];" \
        : "=r"((r)[0]), "=r"((r)[1]), "=r"((r)[2]), "=r"((r)[3]) : "r"(addr))
#define MMA16816(d, a, b0, b1) \
    asm volatile("mma.sync.aligned.m16n8k16.row.col.f32.bf16.bf16.f32 " \
        "{%0,%1,%2,%3},{%4,%5,%6,%7},{%8,%9},{%0,%1,%2,%3};" \
        : "+f"((d)[0]), "+f"((d)[1]), "+f"((d)[2]), "+f"((d)[3]) \
        : "r"((a)[0]), "r"((a)[1]), "r"((a)[2]), "r"((a)[3]), "r"(b0), "r"(b1))

static __device__ __forceinline__ uint32_t mono_f32(float f) {
    uint32_t b = __float_as_uint(f);
    return (b & 0x80000000u) ? ~b : (b | 0x80000000u);
}
static __device__ __forceinline__ ull umax64(ull a, ull b) { return a > b ? a : b; }
static __device__ __forceinline__ ull umin64(ull a, ull b) { return a < b ? a : b; }

// ================= prep: z -> bf16 token-major =================
__global__ void convA_kernel(const float* __restrict__ z) {
    int t = blockIdx.x * 256 + threadIdx.x;
    int token = t >> 5, c8 = t & 31;
    int bb = token >> 10, p = token & 1023;
    __align__(16) __nv_bfloat16 h[8];
    #pragma unroll
    for (int i = 0; i < 8; i++)
        h[i] = __float2bfloat16(z[((size_t)bb * CD + c8 * 8 + i) * HW + p]);
    *(uint4*)&g_Ah[(size_t)token * CD + c8 * 8] = *(const uint4*)h;
}

// ================= prep: codebook -> bf16 + exact 0.5||e||^2 =================
__global__ void convBH_kernel(const float* __restrict__ cb) {
    int t = blockIdx.x * 256 + threadIdx.x;
    int n = t >> 5, c8 = t & 31;
    __align__(16) __nv_bfloat16 h[8];
    float s = 0.f;
    #pragma unroll
    for (int i = 0; i < 8; i++) {
        float v = cb[(size_t)n * CD + c8 * 8 + i];
        h[i] = __float2bfloat16(v);
        s = fmaf(v, v, s);
    }
    *(uint4*)&g_Bh[(size_t)n * CD + c8 * 8] = *(const uint4*)h;
    #pragma unroll
    for (int o = 16; o; o >>= 1) s += __shfl_xor_sync(0xffffffffu, s, o);
    if ((t & 31) == 0) g_hn[n] = 0.5f * s;
}

// ================= tensor-core VQ GEMM (nomination pass) =================
__global__ void __launch_bounds__(256, 1) vq_gemm() {
    extern __shared__ unsigned char smem[];
    const uint32_t sb = smem_u32(smem);
    const int tid = threadIdx.x;
    const int lane = tid & 31;
    const int wid = tid >> 5;
    const int wm = wid >> 2, wn = wid & 3;   // 2 x 4 warps, each 64m x 64n
    const int ngrp  = blockIdx.x;            // 32 groups of 512 codes
    const int mtile = blockIdx.y;            // 32 tiles of 128 tokens

    const char* Abase = (const char*)(g_Ah + (size_t)mtile * 128 * CD);
    const char* Bbase = (const char*)(g_Bh + (size_t)ngrp * 512 * CD);

    // ---- prologue: resident A (128x256 bf16) ----
    {
        const int row = tid & 127, half = tid >> 7;
        const char* asrc = Abase + (size_t)row * 512 + half * 256;
        const uint32_t adst = sb + row * AROW + half * 256;
        #pragma unroll
        for (int j = 0; j < 16; j++)
            cp16(adst + j * 16, asrc + j * 16);
    }
    // ---- B slices: one row (128B) per thread per slice ----
    const uint32_t bdst = sb + APLANE + tid * BROW;
    {
        const char* bsrc0 = Bbase + (size_t)tid * 512;          // nt=0, ks=0
        #pragma unroll
        for (int j = 0; j < 8; j++) cp16(bdst + j * 16, bsrc0 + j * 16);
        cp_commit();
        const char* bsrc1 = Bbase + (size_t)tid * 512 + 128;    // nt=0, ks=1
        #pragma unroll
        for (int j = 0; j < 8; j++) cp16(bdst + BTILE + j * 16, bsrc1 + j * 16);
        cp_commit();
    }

    float acc[4][8][4];
    #pragma unroll
    for (int mi = 0; mi < 4; mi++)
        #pragma unroll
        for (int ni = 0; ni < 8; ni++)
            #pragma unroll
            for (int c = 0; c < 4; c++) acc[mi][ni][c] = 0.f;

    ull k1[4][2], k2[4][2];
    #pragma unroll
    for (int mi = 0; mi < 4; mi++)
        #pragma unroll
        for (int h = 0; h < 2; h++) { k1[mi][h] = 0; k2[mi][h] = 0; }

    const uint32_t a_addr = sb + (wm * 64 + (lane & 15)) * AROW + (lane >> 4) * 16;
    const uint32_t b_addr = sb + APLANE + (wn * 64 + (lane & 15)) * BROW + (lane >> 4) * 16;
    const int cc = (lane & 3) * 2;

    for (int siter = 0; siter < 8; siter++) {
        const int s = siter & 1;
        const int nt = siter >> 2, ks = siter & 3;

        cp_wait<1>();
        __syncthreads();

        const uint32_t bb = b_addr + s * BTILE;
        const uint32_t aa = a_addr + ks * 128;
        #pragma unroll
        for (int kk = 0; kk < 4; kk++) {
            uint32_t a[4][4], b[4][4];
            #pragma unroll
            for (int mi = 0; mi < 4; mi++)
                LDSM4(a[mi], aa + mi * 16 * AROW + kk * 32);
            #pragma unroll
            for (int nf = 0; nf < 4; nf++)
                LDSM4(b[nf], bb + nf * 16 * BROW + kk * 32);
            #pragma unroll
            for (int mi = 0; mi < 4; mi++)
                #pragma unroll
                for (int nf = 0; nf < 4; nf++) {
                    MMA16816(acc[mi][nf * 2 + 0], a[mi], b[nf][0], b[nf][2]);
                    MMA16816(acc[mi][nf * 2 + 1], a[mi], b[nf][1], b[nf][3]);
                }
        }
        __syncthreads();

        // prefetch slice siter+2 into stage s
        const int nsi = siter + 2;
        if (nsi < 8) {
            const int nnt = nsi >> 2, nks = nsi & 3;
            const char* bsrc = Bbase + (size_t)(nnt * 256 + tid) * 512 + nks * 128;
            #pragma unroll
            for (int j = 0; j < 8; j++) cp16(bdst + s * BTILE + j * 16, bsrc + j * 16);
        }
        cp_commit();

        // ntile boundary: fold into persistent top-2, reset acc
        if (ks == 3) {
            const int nbase = ngrp * 512 + nt * 256 + wn * 64;
            #pragma unroll
            for (int ni = 0; ni < 8; ni++) {
                #pragma unroll
                for (int c = 0; c < 2; c++) {
                    const int n = nbase + ni * 8 + cc + c;
                    const float hn = __ldg(&g_hn[n]);
                    const ull lowkey = (ull)(NE - 1 - n);
                    #pragma unroll
                    for (int mi = 0; mi < 4; mi++)
                        #pragma unroll
                        for (int h = 0; h < 2; h++) {
                            const float sc = acc[mi][ni][h * 2 + c] - hn;
                            const ull key = ((ull)mono_f32(sc) << 32) | lowkey;
                            if (key > k1[mi][h]) { k2[mi][h] = k1[mi][h]; k1[mi][h] = key; }
                            else if (key > k2[mi][h]) { k2[mi][h] = key; }
                            acc[mi][ni][h * 2 + c] = 0.f;
                        }
                }
            }
        }
    }

    // quad-reduce top-2 and publish (2 keys per token per wn)
    #pragma unroll
    for (int mi = 0; mi < 4; mi++)
        #pragma unroll
        for (int h = 0; h < 2; h++) {
            ull a1 = k1[mi][h], a2 = k2[mi][h];
            #pragma unroll
            for (int off = 1; off <= 2; off <<= 1) {
                ull o1 = __shfl_xor_sync(0xffffffffu, a1, off);
                ull o2 = __shfl_xor_sync(0xffffffffu, a2, off);
                ull n1 = umax64(a1, o1);
                ull n2 = umax64(umin64(a1, o1), umax64(a2, o2));
                a1 = n1; a2 = n2;
            }
            if ((lane & 3) == 0) {
                const int token = mtile * 128 + wm * 64 + mi * 16 + h * 8 + (lane >> 2);
                ull* dst = g_top + (size_t)token * 256 + ngrp * 8 + wn * 2;
                dst[0] = a1;
                dst[1] = a2;
            }
        }
}

// ================= fixup: global top-4 + exact fp32 rescore =================
__global__ void fixup_kernel(const float* __restrict__ z, const float* __restrict__ cb) {
    const int token = blockIdx.x * 8 + (threadIdx.x >> 5);
    const int lane = threadIdx.x & 31;

    const ull* tp = g_top + (size_t)token * 256;
    ull k[8];
    #pragma unroll
    for (int i = 0; i < 8; i++) k[i] = tp[lane + 32 * i];

    int cand[4];
    #pragma unroll
    for (int r = 0; r < 4; r++) {
        ull m = 0;
        #pragma unroll
        for (int i = 0; i < 8; i++) m = umax64(m, k[i]);
        #pragma unroll
        for (int off = 16; off; off >>= 1)
            m = umax64(m, __shfl_xor_sync(0xffffffffu, m, off));
        #pragma unroll
        for (int i = 0; i < 8; i++) if (k[i] == m) k[i] = 0;
        cand[r] = (NE - 1) - (int)(m & 0xFFFFFFFFull);
    }

    const int bb = token >> 10, p = token & 1023;
    float zv[8];
    #pragma unroll
    for (int i = 0; i < 8; i++)
        zv[i] = z[((size_t)bb * CD + lane + 32 * i) * HW + p];

    ull bestk = 0;
    #pragma unroll
    for (int r = 0; r < 4; r++) {
        const int n = cand[r];
        const float* crow = cb + (size_t)n * CD;
        float s = 0.f;
        #pragma unroll
        for (int i = 0; i < 8; i++) s = fmaf(zv[i], __ldg(&crow[lane + 32 * i]), s);
        #pragma unroll
        for (int off = 16; off; off >>= 1) s += __shfl_xor_sync(0xffffffffu, s, off);
        s -= g_hn[n];
        const ull key = ((ull)mono_f32(s) << 32) | (ull)(NE - 1 - n);
        bestk = umax64(bestk, key);
    }
    if (lane == 0) g_best[token] = (NE - 1) - (int)(bestk & 0xFFFFFFFFull);
}

// ================= gather z_q + spherical distance (fused) =================
__global__ void gather_sph_kernel(const float* __restrict__ cb, const float* __restrict__ ie,
                                  const float* __restrict__ pr, float* __restrict__ out) {
    if (blockIdx.x < NTOK / 32) {
        const int tid = threadIdx.x;
        const int w = tid >> 5, l = tid & 31;
        const int token = blockIdx.x * 32 + l;
        const int n = g_best[token];
        const int bb = token >> 10, p = token & 1023;
        const float* crow = cb + (size_t)n * CD;
        float* ob = out + (size_t)bb * CD * HW + p;
        #pragma unroll 4
        for (int i = 0; i < 32; i++) {
            const int c = w + 8 * i;
            ob[(size_t)c * HW] = crow[c];
        }
        return;
    }
    const int e = (blockIdx.x - NTOK / 32) * 256 + threadIdx.x;
    if (e >= EMB) return;
    float pv[BATCH];
    float pn = 0.f;
    #pragma unroll
    for (int b = 0; b < BATCH; b++) { pv[b] = pr[b * EMB + e]; pn += pv[b] * pv[b]; }
    pn = fmaxf(sqrtf(pn), 1e-12f);
    #pragma unroll
    for (int b = 0; b < BATCH; b++) pv[b] /= pn;
    float acc = 0.f;
    for (int j = 0; j < NCUTS; j++) {
        float q[BATCH];
        float qn = 0.f;
        #pragma unroll
        for (int b = 0; b < BATCH; b++) {
            q[b] = ie[(size_t)(j * BATCH + b) * EMB + e];
            qn += q[b] * q[b];
        }
        qn = fmaxf(sqrtf(qn), 1e-12f);
        float d2 = 0.f;
        #pragma unroll
        for (int b = 0; b < BATCH; b++) {
            float df = q[b] / qn - pv[b];
            d2 += df * df;
        }
        float h = fminf(0.5f * sqrtf(d2), 1.0f);
        float a = asinf(h);
        acc += 2.0f * a * a;
    }
    out[ZQ_N + e] = acc * (1.0f / NCUTS);
}

// ================= launch =================
extern "C" void kernel_launch(void* const* d_in, const int* in_sizes, int n_in,
                              void* d_out, int out_size) {
    const float* z  = (const float*)d_in[0];
    const float* cb = (const float*)d_in[1];
    const float* ie = (const float*)d_in[2];
    const float* pr = (const float*)d_in[3];
    float* out = (float*)d_out;

    cudaFuncSetAttribute(vq_gemm, cudaFuncAttributeMaxDynamicSharedMemorySize, SMEM_B);

    convA_kernel<<<(NTOK * 32) / 256, 256>>>(z);
    convBH_kernel<<<(NE * 32) / 256, 256>>>(cb);
    vq_gemm<<<dim3(NE / 512, NTOK / 128), 256, SMEM_B>>>();
    fixup_kernel<<<NTOK / 8, 256>>>(z, cb);
    gather_sph_kernel<<<NTOK / 32 + 2, 256>>>(cb, ie, pr, out);
}

// round 6
// speedup vs baseline: 1.1246x; 1.1246x over previous
#include <cuda_runtime.h>
#include <cuda_bf16.h>
#include <cstdint>
#include <math.h>

typedef unsigned long long ull;

// ---------------- problem dims ----------------
#define NE     16384
#define CD     256
#define HW     1024
#define NTOK   4096
#define ZQ_N   (NTOK * CD)
#define NCUTS  32
#define EMB    512
#define BATCH  4

// ---------------- GEMM tiling ----------------
// CTA: 64 tokens x 512 codes; 8 warps (2 wm x 4 wn) of 32x32; A resident;
// B streamed as 128-code x 64-k slices, double buffered. 3 CTAs/SM.
#define AROW    528                   // 512B data + 16B pad
#define APLANE  (64 * AROW)           // 33792
#define BROW    144                   // 128B data + 16B pad
#define BTILE   (128 * BROW)          // 18432
#define SMEM_B  (APLANE + 2 * BTILE)  // 70656

// ---------------- device globals ----------------
__device__ __align__(16) __nv_bfloat16 g_Ah[NTOK * CD];
__device__ __align__(16) __nv_bfloat16 g_Bh[NE * CD];
__device__ float g_hn[NE];
__device__ ull   g_top[(size_t)NTOK * 64];    // top-2 per (token, 512-code group)
__device__ int   g_best[NTOK];

// ---------------- asm helpers ----------------
static __device__ __forceinline__ uint32_t smem_u32(const void* p) {
    uint32_t a;
    asm("{ .reg .u64 t; cvta.to.shared.u64 t, %1; cvt.u32.u64 %0, t; }" : "=r"(a) : "l"(p));
    return a;
}
static __device__ __forceinline__ void cp16(uint32_t dst, const void* src) {
    asm volatile("cp.async.cg.shared.global [%0], [%1], 16;" :: "r"(dst), "l"(src));
}
static __device__ __forceinline__ void cp_commit() {
    asm volatile("cp.async.commit_group;");
}
template <int N> static __device__ __forceinline__ void cp_wait() {
    asm volatile("cp.async.wait_group %0;" :: "n"(N));
}
#define LDSM4(r, addr) \
    asm volatile("ldmatrix.sync.aligned.m8n8.x4.shared.b16 {%0,%1,%2,%3}, [%4];" \
        : "=r"((r)[0]), "=r"((r)[1]), "=r"((r)[2]), "=r"((r)[3]) : "r"(addr))
#define MMA16816(d, a, b0, b1) \
    asm volatile("mma.sync.aligned.m16n8k16.row.col.f32.bf16.bf16.f32 " \
        "{%0,%1,%2,%3},{%4,%5,%6,%7},{%8,%9},{%0,%1,%2,%3};" \
        : "+f"((d)[0]), "+f"((d)[1]), "+f"((d)[2]), "+f"((d)[3]) \
        : "r"((a)[0]), "r"((a)[1]), "r"((a)[2]), "r"((a)[3]), "r"(b0), "r"(b1))

static __device__ __forceinline__ uint32_t mono_f32(float f) {
    uint32_t b = __float_as_uint(f);
    return b ^ ((uint32_t)(((int)b) >> 31) | 0x80000000u);
}
static __device__ __forceinline__ ull umax64(ull a, ull b) { return a > b ? a : b; }
static __device__ __forceinline__ ull umin64(ull a, ull b) { return a < b ? a : b; }

// ================= prep: fused z/codebook -> bf16 (+ exact half-norms) =================
#define A_BLKS ((NTOK * 32) / 256)     // 512
#define B_BLKS ((NE * 32) / 256)       // 2048
__global__ void convAB_kernel(const float* __restrict__ z, const float* __restrict__ cb) {
    if (blockIdx.x < A_BLKS) {
        int t = blockIdx.x * 256 + threadIdx.x;
        int token = t >> 5, c8 = t & 31;
        int bb = token >> 10, p = token & 1023;
        __align__(16) __nv_bfloat16 h[8];
        #pragma unroll
        for (int i = 0; i < 8; i++)
            h[i] = __float2bfloat16(z[((size_t)bb * CD + c8 * 8 + i) * HW + p]);
        *(uint4*)&g_Ah[(size_t)token * CD + c8 * 8] = *(const uint4*)h;
        return;
    }
    int t = (blockIdx.x - A_BLKS) * 256 + threadIdx.x;
    int n = t >> 5, c8 = t & 31;
    __align__(16) __nv_bfloat16 h[8];
    float s = 0.f;
    #pragma unroll
    for (int i = 0; i < 8; i++) {
        float v = cb[(size_t)n * CD + c8 * 8 + i];
        h[i] = __float2bfloat16(v);
        s = fmaf(v, v, s);
    }
    *(uint4*)&g_Bh[(size_t)n * CD + c8 * 8] = *(const uint4*)h;
    #pragma unroll
    for (int o = 16; o; o >>= 1) s += __shfl_xor_sync(0xffffffffu, s, o);
    if ((t & 31) == 0) g_hn[n] = 0.5f * s;
}

// ================= tensor-core VQ GEMM (nomination pass) =================
__global__ void __launch_bounds__(256, 3) vq_gemm() {
    extern __shared__ unsigned char smem[];
    const uint32_t sb = smem_u32(smem);
    const int tid = threadIdx.x;
    const int lane = tid & 31;
    const int wid = tid >> 5;
    const int wm = wid >> 2, wn = wid & 3;   // 2 x 4 warps, each 32m x 32n
    const int ngrp  = blockIdx.x;            // 32 groups of 512 codes
    const int mtile = blockIdx.y;            // 64 tiles of 64 tokens

    const char* Abase = (const char*)(g_Ah + (size_t)mtile * 64 * CD);
    const char* Bbase = (const char*)(g_Bh + (size_t)ngrp * 512 * CD);

    // ---- prologue: resident A (64x256 bf16 = 32KB) ----
    {
        const int row = tid >> 2, part = tid & 3;
        const char* asrc = Abase + (size_t)row * 512 + part * 128;
        const uint32_t adst = sb + row * AROW + part * 128;
        #pragma unroll
        for (int j = 0; j < 8; j++)
            cp16(adst + j * 16, asrc + j * 16);
    }
    // ---- B slices: 128 rows, 2 threads/row (64B halves) ----
    const int brow = tid >> 1, bhalf = (tid & 1) * 64;
    const uint32_t bdst = sb + APLANE + brow * BROW + bhalf;
    {
        const char* s0 = Bbase + (size_t)brow * 512 + bhalf;          // nt=0, ks=0
        #pragma unroll
        for (int j = 0; j < 4; j++) cp16(bdst + j * 16, s0 + j * 16);
        cp_commit();
        const char* s1 = Bbase + (size_t)brow * 512 + 128 + bhalf;    // nt=0, ks=1
        #pragma unroll
        for (int j = 0; j < 4; j++) cp16(bdst + BTILE + j * 16, s1 + j * 16);
        cp_commit();
    }

    float acc[2][4][4];
    #pragma unroll
    for (int mi = 0; mi < 2; mi++)
        #pragma unroll
        for (int ni = 0; ni < 4; ni++)
            #pragma unroll
            for (int c = 0; c < 4; c++) acc[mi][ni][c] = 0.f;

    ull k1[2][2], k2[2][2];
    #pragma unroll
    for (int mi = 0; mi < 2; mi++)
        #pragma unroll
        for (int h = 0; h < 2; h++) { k1[mi][h] = 0; k2[mi][h] = 0; }

    const uint32_t a_addr = sb + (wm * 32 + (lane & 15)) * AROW + (lane >> 4) * 16;
    const uint32_t b_addr = sb + APLANE + (wn * 32 + (lane & 15)) * BROW + (lane >> 4) * 16;
    const int cc = (lane & 3) * 2;

    for (int siter = 0; siter < 16; siter++) {
        const int s = siter & 1;
        const int nt = siter >> 2, ks = siter & 3;

        cp_wait<1>();
        __syncthreads();

        const uint32_t bb = b_addr + s * BTILE;
        const uint32_t aa = a_addr + ks * 128;
        #pragma unroll
        for (int kk = 0; kk < 4; kk++) {
            uint32_t a[2][4], b[2][4];
            #pragma unroll
            for (int mi = 0; mi < 2; mi++)
                LDSM4(a[mi], aa + mi * 16 * AROW + kk * 32);
            #pragma unroll
            for (int nf = 0; nf < 2; nf++)
                LDSM4(b[nf], bb + nf * 16 * BROW + kk * 32);
            #pragma unroll
            for (int mi = 0; mi < 2; mi++)
                #pragma unroll
                for (int nf = 0; nf < 2; nf++) {
                    MMA16816(acc[mi][nf * 2 + 0], a[mi], b[nf][0], b[nf][2]);
                    MMA16816(acc[mi][nf * 2 + 1], a[mi], b[nf][1], b[nf][3]);
                }
        }
        __syncthreads();

        // prefetch slice siter+2 into stage s
        const int nsi = siter + 2;
        if (nsi < 16) {
            const int nnt = nsi >> 2, nks = nsi & 3;
            const char* bsrc = Bbase + (size_t)(nnt * 128 + brow) * 512 + nks * 128 + bhalf;
            #pragma unroll
            for (int j = 0; j < 4; j++) cp16(bdst + s * BTILE + j * 16, bsrc + j * 16);
        }
        cp_commit();

        // ntile boundary: fold into persistent top-2, reset acc
        if (ks == 3) {
            const int nbase = ngrp * 512 + nt * 128 + wn * 32;
            #pragma unroll
            for (int ni = 0; ni < 4; ni++) {
                #pragma unroll
                for (int c = 0; c < 2; c++) {
                    const int n = nbase + ni * 8 + cc + c;
                    const float hn = __ldg(&g_hn[n]);
                    const ull lowkey = (ull)(NE - 1 - n);
                    #pragma unroll
                    for (int mi = 0; mi < 2; mi++)
                        #pragma unroll
                        for (int h = 0; h < 2; h++) {
                            const float sc = acc[mi][ni][h * 2 + c] - hn;
                            const ull key = ((ull)mono_f32(sc) << 32) | lowkey;
                            if (key > k1[mi][h]) { k2[mi][h] = k1[mi][h]; k1[mi][h] = key; }
                            else if (key > k2[mi][h]) { k2[mi][h] = key; }
                            acc[mi][ni][h * 2 + c] = 0.f;
                        }
                }
            }
        }
    }

    // ---- quad-reduce top-2, stash per (token, wn) in smem (reuse B stage0) ----
    ull* red = (ull*)(smem + APLANE);   // [64 tokens][4 wn][2]
    #pragma unroll
    for (int mi = 0; mi < 2; mi++)
        #pragma unroll
        for (int h = 0; h < 2; h++) {
            ull a1 = k1[mi][h], a2 = k2[mi][h];
            #pragma unroll
            for (int off = 1; off <= 2; off <<= 1) {
                ull o1 = __shfl_xor_sync(0xffffffffu, a1, off);
                ull o2 = __shfl_xor_sync(0xffffffffu, a2, off);
                ull n1 = umax64(a1, o1);
                ull n2 = umax64(umin64(a1, o1), umax64(a2, o2));
                a1 = n1; a2 = n2;
            }
            if ((lane & 3) == 0) {
                const int tl = wm * 32 + mi * 16 + h * 8 + (lane >> 2);
                red[tl * 8 + wn * 2 + 0] = a1;
                red[tl * 8 + wn * 2 + 1] = a2;
            }
        }
    __syncthreads();

    // ---- cross-wn reduce: top-2 per token over 8 keys, publish ----
    if (tid < 64) {
        ull b1 = 0, b2 = 0;
        #pragma unroll
        for (int j = 0; j < 8; j++) {
            const ull k = red[tid * 8 + j];
            if (k > b1) { b2 = b1; b1 = k; }
            else if (k > b2) { b2 = k; }
        }
        ull* dst = g_top + (size_t)(mtile * 64 + tid) * 64 + ngrp * 2;
        dst[0] = b1;
        dst[1] = b2;
    }
}

// ================= fixup: global top-4 + exact fp32 rescore =================
__global__ void fixup_kernel(const float* __restrict__ z, const float* __restrict__ cb) {
    const int token = blockIdx.x * 8 + (threadIdx.x >> 5);
    const int lane = threadIdx.x & 31;

    const ull* tp = g_top + (size_t)token * 64;
    ull k[2];
    k[0] = tp[lane];
    k[1] = tp[lane + 32];

    int cand[4];
    #pragma unroll
    for (int r = 0; r < 4; r++) {
        ull m = umax64(k[0], k[1]);
        #pragma unroll
        for (int off = 16; off; off >>= 1)
            m = umax64(m, __shfl_xor_sync(0xffffffffu, m, off));
        if (k[0] == m) k[0] = 0;
        if (k[1] == m) k[1] = 0;
        cand[r] = (NE - 1) - (int)(m & 0xFFFFFFFFull);
    }

    const int bb = token >> 10, p = token & 1023;
    float zv[8];
    #pragma unroll
    for (int i = 0; i < 8; i++)
        zv[i] = z[((size_t)bb * CD + lane + 32 * i) * HW + p];

    ull bestk = 0;
    #pragma unroll
    for (int r = 0; r < 4; r++) {
        const int n = cand[r];
        const float* crow = cb + (size_t)n * CD;
        float s = 0.f;
        #pragma unroll
        for (int i = 0; i < 8; i++) s = fmaf(zv[i], __ldg(&crow[lane + 32 * i]), s);
        #pragma unroll
        for (int off = 16; off; off >>= 1) s += __shfl_xor_sync(0xffffffffu, s, off);
        s -= g_hn[n];
        const ull key = ((ull)mono_f32(s) << 32) | (ull)(NE - 1 - n);
        bestk = umax64(bestk, key);
    }
    if (lane == 0) g_best[token] = (NE - 1) - (int)(bestk & 0xFFFFFFFFull);
}

// ================= gather z_q + spherical distance (fused) =================
__global__ void gather_sph_kernel(const float* __restrict__ cb, const float* __restrict__ ie,
                                  const float* __restrict__ pr, float* __restrict__ out) {
    if (blockIdx.x < NTOK / 32) {
        const int tid = threadIdx.x;
        const int w = tid >> 5, l = tid & 31;
        const int token = blockIdx.x * 32 + l;
        const int n = g_best[token];
        const int bb = token >> 10, p = token & 1023;
        const float* crow = cb + (size_t)n * CD;
        float* ob = out + (size_t)bb * CD * HW + p;
        #pragma unroll 4
        for (int i = 0; i < 32; i++) {
            const int c = w + 8 * i;
            ob[(size_t)c * HW] = crow[c];
        }
        return;
    }
    const int e = (blockIdx.x - NTOK / 32) * 256 + threadIdx.x;
    if (e >= EMB) return;
    float pv[BATCH];
    float pn = 0.f;
    #pragma unroll
    for (int b = 0; b < BATCH; b++) { pv[b] = pr[b * EMB + e]; pn += pv[b] * pv[b]; }
    pn = fmaxf(sqrtf(pn), 1e-12f);
    #pragma unroll
    for (int b = 0; b < BATCH; b++) pv[b] /= pn;
    float acc = 0.f;
    for (int j = 0; j < NCUTS; j++) {
        float q[BATCH];
        float qn = 0.f;
        #pragma unroll
        for (int b = 0; b < BATCH; b++) {
            q[b] = ie[(size_t)(j * BATCH + b) * EMB + e];
            qn += q[b] * q[b];
        }
        qn = fmaxf(sqrtf(qn), 1e-12f);
        float d2 = 0.f;
        #pragma unroll
        for (int b = 0; b < BATCH; b++) {
            float df = q[b] / qn - pv[b];
            d2 += df * df;
        }
        float h = fminf(0.5f * sqrtf(d2), 1.0f);
        float a = asinf(h);
        acc += 2.0f * a * a;
    }
    out[ZQ_N + e] = acc * (1.0f / NCUTS);
}

// ================= launch =================
extern "C" void kernel_launch(void* const* d_in, const int* in_sizes, int n_in,
                              void* d_out, int out_size) {
    const float* z  = (const float*)d_in[0];
    const float* cb = (const float*)d_in[1];
    const float* ie = (const float*)d_in[2];
    const float* pr = (const float*)d_in[3];
    float* out = (float*)d_out;

    cudaFuncSetAttribute(vq_gemm, cudaFuncAttributeMaxDynamicSharedMemorySize, SMEM_B);

    convAB_kernel<<<A_BLKS + B_BLKS, 256>>>(z, cb);
    vq_gemm<<<dim3(NE / 512, NTOK / 64), 256, SMEM_B>>>();
    fixup_kernel<<<NTOK / 8, 256>>>(z, cb);
    gather_sph_kernel<<<NTOK / 32 + 2, 256>>>(cb, ie, pr, out);
}

// round 8
// speedup vs baseline: 1.3919x; 1.2377x over previous
#include <cuda_runtime.h>
#include <cuda_bf16.h>
#include <cstdint>
#include <math.h>

typedef unsigned long long ull;

// ---------------- problem dims ----------------
#define NE     16384
#define CD     256
#define HW     1024
#define NTOK   4096
#define ZQ_N   (NTOK * CD)
#define NCUTS  32
#define EMB    512
#define BATCH  4

// ---------------- GEMM tiling ----------------
// CTA: 128 tokens x 512 codes; 8 warps (4 wm x 2 wn) of 32x64.
// A resident (128x256 bf16, XOR-swizzled, 64KB); B streamed as 16 slices of
// 128 codes x 64 k (16KB, XOR-swizzled), 3-stage pipeline, 1 sync/iter. 2 CTA/SM.
#define APLANE  65536
#define BTILE   16384
#define NSLICES 16
#define SMEM_B  (APLANE + 3 * BTILE)   // 114688

// ---------------- device globals ----------------
__device__ __align__(16) __nv_bfloat16 g_Ah[NTOK * CD];
__device__ __align__(16) __nv_bfloat16 g_Bh[NE * CD];
__device__ __align__(16) float g_zt[NTOK * CD];      // fp32 z, token-major (for fixup)
__device__ float g_hn[NE];
__device__ ull   g_top[(size_t)NTOK * 128];
__device__ int   g_best[NTOK];

// ---------------- asm helpers ----------------
static __device__ __forceinline__ uint32_t smem_u32(const void* p) {
    uint32_t a;
    asm("{ .reg .u64 t; cvta.to.shared.u64 t, %1; cvt.u32.u64 %0, t; }" : "=r"(a) : "l"(p));
    return a;
}
static __device__ __forceinline__ void cp16(uint32_t dst, const void* src) {
    asm volatile("cp.async.cg.shared.global [%0], [%1], 16;" :: "r"(dst), "l"(src));
}
static __device__ __forceinline__ void cp_commit() {
    asm volatile("cp.async.commit_group;");
}
template <int N> static __device__ __forceinline__ void cp_wait() {
    asm volatile("cp.async.wait_group %0;" :: "n"(N));
}
#define LDSM4(r, addr) \
    asm volatile("ldmatrix.sync.aligned.m8n8.x4.shared.b16 {%0,%1,%2,%3}, [%4];" \
        : "=r"((r)[0]), "=r"((r)[1]), "=r"((r)[2]), "=r"((r)[3]) : "r"(addr))
#define MMA16816(d, a, b0, b1) \
    asm volatile("mma.sync.aligned.m16n8k16.row.col.f32.bf16.bf16.f32 " \
        "{%0,%1,%2,%3},{%4,%5,%6,%7},{%8,%9},{%0,%1,%2,%3};" \
        : "+f"((d)[0]), "+f"((d)[1]), "+f"((d)[2]), "+f"((d)[3]) \
        : "r"((a)[0]), "r"((a)[1]), "r"((a)[2]), "r"((a)[3]), "r"(b0), "r"(b1))

static __device__ __forceinline__ uint32_t mono_f32(float f) {
    uint32_t b = __float_as_uint(f);
    return b ^ ((uint32_t)(((int)b) >> 31) | 0x80000000u);
}
static __device__ __forceinline__ ull umax64(ull a, ull b) { return a > b ? a : b; }
static __device__ __forceinline__ ull umin64(ull a, ull b) { return a < b ? a : b; }

// ================= prep: fused z/codebook -> bf16 (+ fp32 zt, half-norms) =================
#define A_BLKS ((NTOK * 32) / 256)     // 512
#define B_BLKS ((NE * 32) / 256)       // 2048
__global__ void convAB_kernel(const float* __restrict__ z, const float* __restrict__ cb) {
    if (blockIdx.x < A_BLKS) {
        int t = blockIdx.x * 256 + threadIdx.x;
        int token = t >> 5, c8 = t & 31;
        int bb = token >> 10, p = token & 1023;
        __align__(16) __nv_bfloat16 h[8];
        __align__(16) float v[8];
        #pragma unroll
        for (int i = 0; i < 8; i++) {
            v[i] = z[((size_t)bb * CD + c8 * 8 + i) * HW + p];
            h[i] = __float2bfloat16(v[i]);
        }
        *(uint4*)&g_Ah[(size_t)token * CD + c8 * 8] = *(const uint4*)h;
        *(float4*)&g_zt[(size_t)token * CD + c8 * 8]     = *(const float4*)v;
        *(float4*)&g_zt[(size_t)token * CD + c8 * 8 + 4] = *(const float4*)(v + 4);
        return;
    }
    int t = (blockIdx.x - A_BLKS) * 256 + threadIdx.x;
    int n = t >> 5, c8 = t & 31;
    __align__(16) __nv_bfloat16 h[8];
    float s = 0.f;
    #pragma unroll
    for (int i = 0; i < 8; i++) {
        float v = cb[(size_t)n * CD + c8 * 8 + i];
        h[i] = __float2bfloat16(v);
        s = fmaf(v, v, s);
    }
    *(uint4*)&g_Bh[(size_t)n * CD + c8 * 8] = *(const uint4*)h;
    #pragma unroll
    for (int o = 16; o; o >>= 1) s += __shfl_xor_sync(0xffffffffu, s, o);
    if ((t & 31) == 0) g_hn[n] = 0.5f * s;
}

// ================= tensor-core VQ GEMM (nomination pass) =================
__global__ void __launch_bounds__(256, 2) vq_gemm() {
    extern __shared__ unsigned char smem[];
    const uint32_t sb = smem_u32(smem);
    const int tid = threadIdx.x;
    const int lane = tid & 31;
    const int wid = tid >> 5;
    const int wm = wid >> 1, wn = wid & 1;   // 4 x 2 warps, each 32m x 64n
    const int ngrp  = blockIdx.x;            // 32 groups of 512 codes
    const int mtile = blockIdx.y;            // 32 tiles of 128 tokens

    const char* Abase = (const char*)(g_Ah + (size_t)mtile * 128 * CD);
    const char* Bbase = (const char*)(g_Bh + (size_t)ngrp * 512 * CD);

    // ---- loader geometry ----
    const int arow = tid >> 1, ahalf = tid & 1;          // A: 2 thr/row, 256B each
    const int brow = tid >> 1, bhalf = tid & 1;          // B: 2 thr/row, 64B each
    const uint32_t a_sm_row = sb + arow * 512;
    const int ar7l = arow & 7;
    const int br7l = brow & 7;

    // prologue: A (swizzled) + B slices 0,1 as groups G0,G1
    {
        const char* asrc = Abase + (size_t)arow * 512 + ahalf * 256;
        #pragma unroll
        for (int j = 0; j < 16; j++) {
            const int c16 = ahalf * 16 + j;
            const uint32_t dst = a_sm_row + (c16 >> 3) * 128 + (((c16 & 7) ^ ar7l) << 4);
            cp16(dst, asrc + j * 16);
        }
        // slice 0 -> stage 0  (ntile 0, ks 0)
        const char* bsrc0 = Bbase + (size_t)brow * 512 + bhalf * 64;
        #pragma unroll
        for (int j = 0; j < 4; j++) {
            const int c16 = bhalf * 4 + j;
            cp16(sb + APLANE + brow * 128 + ((c16 ^ br7l) << 4), bsrc0 + j * 16);
        }
        cp_commit();                                      // G0 (A + slice0)
        // slice 1 -> stage 1  (ntile 0, ks 1)
        const char* bsrc1 = Bbase + (size_t)brow * 512 + 128 + bhalf * 64;
        #pragma unroll
        for (int j = 0; j < 4; j++) {
            const int c16 = bhalf * 4 + j;
            cp16(sb + APLANE + BTILE + brow * 128 + ((c16 ^ br7l) << 4), bsrc1 + j * 16);
        }
        cp_commit();                                      // G1
    }

    float acc[2][8][4];
    #pragma unroll
    for (int mi = 0; mi < 2; mi++)
        #pragma unroll
        for (int ni = 0; ni < 8; ni++)
            #pragma unroll
            for (int c = 0; c < 4; c++) acc[mi][ni][c] = 0.f;

    ull k1[2][2], k2[2][2];
    #pragma unroll
    for (int mi = 0; mi < 2; mi++)
        #pragma unroll
        for (int h = 0; h < 2; h++) { k1[mi][h] = 0; k2[mi][h] = 0; }

    // ldsm geometry (swizzled)
    const int chi = lane >> 4;                 // k-16B selector within pair
    uint32_t a_row_sm[2]; int ar7[2];
    #pragma unroll
    for (int mi = 0; mi < 2; mi++) {
        const int rowA = wm * 32 + mi * 16 + (lane & 15);
        a_row_sm[mi] = sb + rowA * 512;
        ar7[mi] = rowA & 7;
    }
    uint32_t b_row_off[4]; int br7[4];
    #pragma unroll
    for (int nf = 0; nf < 4; nf++) {
        const int rowB = wn * 64 + nf * 16 + (lane & 15);
        b_row_off[nf] = rowB * 128;
        br7[nf] = rowB & 7;
    }
    const int cc = (lane & 3) * 2;

    int stage = 0;
    for (int siter = 0; siter < NSLICES; siter++) {
        const int nt = siter >> 2, ks = siter & 3;

        if (siter < NSLICES - 2) cp_wait<1>(); else cp_wait<0>();
        __syncthreads();

        // issue slice siter+2 into stage (siter+2)%3 (frees iter-1's stage; sync legalized)
        const int nsi = siter + 2;
        if (nsi < NSLICES) {
            int pst = stage + 2; if (pst >= 3) pst -= 3;
            const int nnt = nsi >> 2, nks = nsi & 3;
            const char* bsrc = Bbase + (size_t)(nnt * 128 + brow) * 512 + nks * 128 + bhalf * 64;
            const uint32_t bdst = sb + APLANE + pst * BTILE + brow * 128;
            #pragma unroll
            for (int j = 0; j < 4; j++) {
                const int c16 = bhalf * 4 + j;
                cp16(bdst + ((c16 ^ br7l) << 4), bsrc + j * 16);
            }
            cp_commit();
        }

        const uint32_t sbB = sb + APLANE + stage * BTILE;
        #pragma unroll
        for (int kk = 0; kk < 4; kk++) {               // FIX: full 128B slice (c16a 0..7)
            uint32_t a[2][4], b[4][4];
            const int c16a = kk * 2 + chi;
            #pragma unroll
            for (int mi = 0; mi < 2; mi++)
                LDSM4(a[mi], a_row_sm[mi] + ks * 128 + ((c16a ^ ar7[mi]) << 4));
            #pragma unroll
            for (int nf = 0; nf < 4; nf++)
                LDSM4(b[nf], sbB + b_row_off[nf] + ((c16a ^ br7[nf]) << 4));
            #pragma unroll
            for (int mi = 0; mi < 2; mi++)
                #pragma unroll
                for (int nf = 0; nf < 4; nf++) {
                    MMA16816(acc[mi][nf * 2 + 0], a[mi], b[nf][0], b[nf][2]);
                    MMA16816(acc[mi][nf * 2 + 1], a[mi], b[nf][1], b[nf][3]);
                }
        }
        if (++stage == 3) stage = 0;

        // ntile boundary: fold into persistent top-2, reset acc
        if (ks == 3) {
            const int nbase = ngrp * 512 + nt * 128 + wn * 64;
            #pragma unroll
            for (int ni = 0; ni < 8; ni++) {
                #pragma unroll
                for (int c = 0; c < 2; c++) {
                    const int n = nbase + ni * 8 + cc + c;
                    const float hn = __ldg(&g_hn[n]);
                    const ull lowkey = (ull)(NE - 1 - n);
                    #pragma unroll
                    for (int mi = 0; mi < 2; mi++)
                        #pragma unroll
                        for (int h = 0; h < 2; h++) {
                            const float sc = acc[mi][ni][h * 2 + c] - hn;
                            const ull key = ((ull)mono_f32(sc) << 32) | lowkey;
                            if (key > k1[mi][h]) { k2[mi][h] = k1[mi][h]; k1[mi][h] = key; }
                            else if (key > k2[mi][h]) { k2[mi][h] = key; }
                            acc[mi][ni][h * 2 + c] = 0.f;
                        }
                }
            }
        }
    }

    // quad-reduce top-2 and publish (2 keys per token per wn)
    #pragma unroll
    for (int mi = 0; mi < 2; mi++)
        #pragma unroll
        for (int h = 0; h < 2; h++) {
            ull a1 = k1[mi][h], a2 = k2[mi][h];
            #pragma unroll
            for (int off = 1; off <= 2; off <<= 1) {
                ull o1 = __shfl_xor_sync(0xffffffffu, a1, off);
                ull o2 = __shfl_xor_sync(0xffffffffu, a2, off);
                ull n1 = umax64(a1, o1);
                ull n2 = umax64(umin64(a1, o1), umax64(a2, o2));
                a1 = n1; a2 = n2;
            }
            if ((lane & 3) == 0) {
                const int token = mtile * 128 + wm * 32 + mi * 16 + h * 8 + (lane >> 2);
                ull* dst = g_top + (size_t)token * 128 + ngrp * 4 + wn * 2;
                dst[0] = a1;
                dst[1] = a2;
            }
        }
}

// ================= fixup: global top-4 + exact fp32 rescore =================
__global__ void fixup_kernel(const float* __restrict__ cb) {
    const int token = blockIdx.x * 8 + (threadIdx.x >> 5);
    const int lane = threadIdx.x & 31;

    const ull* tp = g_top + (size_t)token * 128;
    ull k[4];
    #pragma unroll
    for (int i = 0; i < 4; i++) k[i] = tp[lane + 32 * i];

    int cand[4];
    #pragma unroll
    for (int r = 0; r < 4; r++) {
        ull m = 0;
        #pragma unroll
        for (int i = 0; i < 4; i++) m = umax64(m, k[i]);
        #pragma unroll
        for (int off = 16; off; off >>= 1)
            m = umax64(m, __shfl_xor_sync(0xffffffffu, m, off));
        #pragma unroll
        for (int i = 0; i < 4; i++) if (k[i] == m) k[i] = 0;
        cand[r] = (NE - 1) - (int)(m & 0xFFFFFFFFull);
    }

    float zv[8];
    #pragma unroll
    for (int i = 0; i < 8; i++)
        zv[i] = g_zt[(size_t)token * CD + lane + 32 * i];   // coalesced

    ull bestk = 0;
    #pragma unroll
    for (int r = 0; r < 4; r++) {
        const int n = cand[r];
        const float* crow = cb + (size_t)n * CD;
        float s = 0.f;
        #pragma unroll
        for (int i = 0; i < 8; i++) s = fmaf(zv[i], __ldg(&crow[lane + 32 * i]), s);
        #pragma unroll
        for (int off = 16; off; off >>= 1) s += __shfl_xor_sync(0xffffffffu, s, off);
        s -= g_hn[n];
        const ull key = ((ull)mono_f32(s) << 32) | (ull)(NE - 1 - n);
        bestk = umax64(bestk, key);
    }
    if (lane == 0) g_best[token] = (NE - 1) - (int)(bestk & 0xFFFFFFFFull);
}

// ================= gather z_q (smem transpose) + spherical distance =================
#define GT_BLKS (NTOK / 64)   // 64
__global__ void gather_sph_kernel(const float* __restrict__ cb, const float* __restrict__ ie,
                                  const float* __restrict__ pr, float* __restrict__ out) {
    if (blockIdx.x < GT_BLKS) {
        extern __shared__ float ts[];       // [64][257]
        const int tid = threadIdx.x;
        // phase 1: coalesced codebook row loads -> staged transpose
        const int r = tid >> 2, part = tid & 3;
        const int n = g_best[blockIdx.x * 64 + r];
        const float* crow = cb + (size_t)n * CD + part * 64;
        float* dst = ts + r * 257 + part * 64;
        #pragma unroll
        for (int j = 0; j < 16; j++) {
            float4 v = *(const float4*)(crow + j * 4);
            dst[j * 4 + 0] = v.x; dst[j * 4 + 1] = v.y;
            dst[j * 4 + 2] = v.z; dst[j * 4 + 3] = v.w;
        }
        __syncthreads();
        // phase 2: coalesced stores to [B,C,H,W]
        const int w = tid >> 5, l = tid & 31;
        const int t0 = blockIdx.x * 64;
        const int bb = t0 >> 10, p0 = t0 & 1023;
        float* ob = out + (size_t)bb * CD * HW + p0;
        #pragma unroll
        for (int i = 0; i < 32; i++) {
            const int c = w + 8 * i;
            ob[(size_t)c * HW + l]      = ts[l * 257 + c];
            ob[(size_t)c * HW + 32 + l] = ts[(32 + l) * 257 + c];
        }
        return;
    }
    const int e = (blockIdx.x - GT_BLKS) * 256 + threadIdx.x;
    if (e >= EMB) return;
    float pv[BATCH];
    float pn = 0.f;
    #pragma unroll
    for (int b = 0; b < BATCH; b++) { pv[b] = pr[b * EMB + e]; pn += pv[b] * pv[b]; }
    pn = fmaxf(sqrtf(pn), 1e-12f);
    #pragma unroll
    for (int b = 0; b < BATCH; b++) pv[b] /= pn;
    float acc = 0.f;
    for (int j = 0; j < NCUTS; j++) {
        float q[BATCH];
        float qn = 0.f;
        #pragma unroll
        for (int b = 0; b < BATCH; b++) {
            q[b] = ie[(size_t)(j * BATCH + b) * EMB + e];
            qn += q[b] * q[b];
        }
        qn = fmaxf(sqrtf(qn), 1e-12f);
        float d2 = 0.f;
        #pragma unroll
        for (int b = 0; b < BATCH; b++) {
            float df = q[b] / qn - pv[b];
            d2 += df * df;
        }
        float h = fminf(0.5f * sqrtf(d2), 1.0f);
        float a = asinf(h);
        acc += 2.0f * a * a;
    }
    out[ZQ_N + e] = acc * (1.0f / NCUTS);
}

#define GT_SMEM (64 * 257 * 4)

// ================= launch =================
extern "C" void kernel_launch(void* const* d_in, const int* in_sizes, int n_in,
                              void* d_out, int out_size) {
    const float* z  = (const float*)d_in[0];
    const float* cb = (const float*)d_in[1];
    const float* ie = (const float*)d_in[2];
    const float* pr = (const float*)d_in[3];
    float* out = (float*)d_out;

    cudaFuncSetAttribute(vq_gemm, cudaFuncAttributeMaxDynamicSharedMemorySize, SMEM_B);
    cudaFuncSetAttribute(gather_sph_kernel, cudaFuncAttributeMaxDynamicSharedMemorySize, GT_SMEM);

    convAB_kernel<<<A_BLKS + B_BLKS, 256>>>(z, cb);
    vq_gemm<<<dim3(NE / 512, NTOK / 128), 256, SMEM_B>>>();
    fixup_kernel<<<NTOK / 8, 256>>>(cb);
    gather_sph_kernel<<<GT_BLKS + 2, 256, GT_SMEM>>>(cb, ie, pr, out);
}

// round 9
// speedup vs baseline: 1.4925x; 1.0723x over previous
#include <cuda_runtime.h>
#include <cuda_bf16.h>
#include <cstdint>
#include <math.h>

typedef unsigned long long ull;

// ---------------- problem dims ----------------
#define NE     16384
#define CD     256
#define HW     1024
#define NTOK   4096
#define ZQ_N   (NTOK * CD)
#define NCUTS  32
#define EMB    512
#define BATCH  4

// ---------------- GEMM tiling ----------------
// CTA: 128 tokens x 512 codes; 8 warps (4 wm x 2 wn) of 32x64.
// A resident (128x256 bf16, XOR-swizzled, 64KB); B streamed as 16 slices of
// 128 codes x 64 k (16KB, XOR-swizzled), 3-stage pipeline, 1 sync/iter. 2 CTA/SM.
#define APLANE  65536
#define BTILE   16384
#define NSLICES 16
#define SMEM_B  (APLANE + 3 * BTILE)   // 114688

// ---------------- device globals ----------------
__device__ __align__(16) __nv_bfloat16 g_Ah[NTOK * CD];
__device__ __align__(16) __nv_bfloat16 g_Bh[NE * CD];
__device__ __align__(16) float g_zt[NTOK * CD];      // fp32 z, token-major (for fixup)
__device__ float g_hn[NE];
__device__ ull   g_top[(size_t)NTOK * 128];
__device__ int   g_best[NTOK];

// ---------------- asm helpers ----------------
static __device__ __forceinline__ uint32_t smem_u32(const void* p) {
    uint32_t a;
    asm("{ .reg .u64 t; cvta.to.shared.u64 t, %1; cvt.u32.u64 %0, t; }" : "=r"(a) : "l"(p));
    return a;
}
static __device__ __forceinline__ void cp16(uint32_t dst, const void* src) {
    asm volatile("cp.async.cg.shared.global [%0], [%1], 16;" :: "r"(dst), "l"(src));
}
static __device__ __forceinline__ void cp_commit() {
    asm volatile("cp.async.commit_group;");
}
template <int N> static __device__ __forceinline__ void cp_wait() {
    asm volatile("cp.async.wait_group %0;" :: "n"(N));
}
#define LDSM4(r, addr) \
    asm volatile("ldmatrix.sync.aligned.m8n8.x4.shared.b16 {%0,%1,%2,%3}, [%4];" \
        : "=r"((r)[0]), "=r"((r)[1]), "=r"((r)[2]), "=r"((r)[3]) : "r"(addr))
#define MMA16816(d, a, b0, b1) \
    asm volatile("mma.sync.aligned.m16n8k16.row.col.f32.bf16.bf16.f32 " \
        "{%0,%1,%2,%3},{%4,%5,%6,%7},{%8,%9},{%0,%1,%2,%3};" \
        : "+f"((d)[0]), "+f"((d)[1]), "+f"((d)[2]), "+f"((d)[3]) \
        : "r"((a)[0]), "r"((a)[1]), "r"((a)[2]), "r"((a)[3]), "r"(b0), "r"(b1))

static __device__ __forceinline__ uint32_t mono_f32(float f) {
    uint32_t b = __float_as_uint(f);
    return b ^ ((uint32_t)(((int)b) >> 31) | 0x80000000u);
}
static __device__ __forceinline__ ull umax64(ull a, ull b) { return a > b ? a : b; }
static __device__ __forceinline__ ull umin64(ull a, ull b) { return a < b ? a : b; }

// ================= prep: fused z/codebook -> bf16 (+ fp32 zt, half-norms) =================
// A part: warp gw -> token-group tg = gw>>5 (32 tokens, lane = token), c-octet = gw&31.
// z reads are 128B coalesced; writes scattered 16B (cheap).
#define A_BLKS ((NTOK / 32 * 32) / 8)  // 512 blocks (4096 warps)
#define B_BLKS ((NE * 32) / 256)       // 2048
__global__ void convAB_kernel(const float* __restrict__ z, const float* __restrict__ cb) {
    if (blockIdx.x < A_BLKS) {
        const int gw = blockIdx.x * 8 + (threadIdx.x >> 5);
        const int lane = threadIdx.x & 31;
        const int tg = gw >> 5, c8 = gw & 31;
        const int token = tg * 32 + lane;
        const int bb = token >> 10, p = token & 1023;
        __align__(16) __nv_bfloat16 h[8];
        __align__(16) float v[8];
        #pragma unroll
        for (int i = 0; i < 8; i++) {
            v[i] = z[((size_t)bb * CD + c8 * 8 + i) * HW + p];   // coalesced over lane
            h[i] = __float2bfloat16(v[i]);
        }
        *(uint4*)&g_Ah[(size_t)token * CD + c8 * 8] = *(const uint4*)h;
        *(float4*)&g_zt[(size_t)token * CD + c8 * 8]     = *(const float4*)v;
        *(float4*)&g_zt[(size_t)token * CD + c8 * 8 + 4] = *(const float4*)(v + 4);
        return;
    }
    int t = (blockIdx.x - A_BLKS) * 256 + threadIdx.x;
    int n = t >> 5, c8 = t & 31;
    __align__(16) __nv_bfloat16 h[8];
    float s = 0.f;
    #pragma unroll
    for (int i = 0; i < 8; i++) {
        float v = cb[(size_t)n * CD + c8 * 8 + i];
        h[i] = __float2bfloat16(v);
        s = fmaf(v, v, s);
    }
    *(uint4*)&g_Bh[(size_t)n * CD + c8 * 8] = *(const uint4*)h;
    #pragma unroll
    for (int o = 16; o; o >>= 1) s += __shfl_xor_sync(0xffffffffu, s, o);
    if ((t & 31) == 0) g_hn[n] = 0.5f * s;
}

// ================= tensor-core VQ GEMM (nomination pass) =================
__global__ void __launch_bounds__(256, 2) vq_gemm() {
    extern __shared__ unsigned char smem[];
    const uint32_t sb = smem_u32(smem);
    const int tid = threadIdx.x;
    const int lane = tid & 31;
    const int wid = tid >> 5;
    const int wm = wid >> 1, wn = wid & 1;   // 4 x 2 warps, each 32m x 64n
    const int ngrp  = blockIdx.x;            // 32 groups of 512 codes
    const int mtile = blockIdx.y;            // 32 tiles of 128 tokens

    const char* Abase = (const char*)(g_Ah + (size_t)mtile * 128 * CD);
    const char* Bbase = (const char*)(g_Bh + (size_t)ngrp * 512 * CD);

    // ---- loader geometry ----
    const int arow = tid >> 1, ahalf = tid & 1;          // A: 2 thr/row, 256B each
    const int brow = tid >> 1, bhalf = tid & 1;          // B: 2 thr/row, 64B each
    const uint32_t a_sm_row = sb + arow * 512;
    const int ar7l = arow & 7;
    const int br7l = brow & 7;

    // prologue: A (swizzled) + B slices 0,1 as groups G0,G1
    {
        const char* asrc = Abase + (size_t)arow * 512 + ahalf * 256;
        #pragma unroll
        for (int j = 0; j < 16; j++) {
            const int c16 = ahalf * 16 + j;
            const uint32_t dst = a_sm_row + (c16 >> 3) * 128 + (((c16 & 7) ^ ar7l) << 4);
            cp16(dst, asrc + j * 16);
        }
        const char* bsrc0 = Bbase + (size_t)brow * 512 + bhalf * 64;
        #pragma unroll
        for (int j = 0; j < 4; j++) {
            const int c16 = bhalf * 4 + j;
            cp16(sb + APLANE + brow * 128 + ((c16 ^ br7l) << 4), bsrc0 + j * 16);
        }
        cp_commit();                                      // G0 (A + slice0)
        const char* bsrc1 = Bbase + (size_t)brow * 512 + 128 + bhalf * 64;
        #pragma unroll
        for (int j = 0; j < 4; j++) {
            const int c16 = bhalf * 4 + j;
            cp16(sb + APLANE + BTILE + brow * 128 + ((c16 ^ br7l) << 4), bsrc1 + j * 16);
        }
        cp_commit();                                      // G1
    }

    float acc[2][8][4];
    #pragma unroll
    for (int mi = 0; mi < 2; mi++)
        #pragma unroll
        for (int ni = 0; ni < 8; ni++)
            #pragma unroll
            for (int c = 0; c < 4; c++) acc[mi][ni][c] = 0.f;

    ull k1[2][2], k2[2][2];
    #pragma unroll
    for (int mi = 0; mi < 2; mi++)
        #pragma unroll
        for (int h = 0; h < 2; h++) { k1[mi][h] = 0; k2[mi][h] = 0; }

    // ldsm geometry (swizzled)
    const int chi = lane >> 4;
    uint32_t a_row_sm[2]; int ar7[2];
    #pragma unroll
    for (int mi = 0; mi < 2; mi++) {
        const int rowA = wm * 32 + mi * 16 + (lane & 15);
        a_row_sm[mi] = sb + rowA * 512;
        ar7[mi] = rowA & 7;
    }
    uint32_t b_row_off[4]; int br7[4];
    #pragma unroll
    for (int nf = 0; nf < 4; nf++) {
        const int rowB = wn * 64 + nf * 16 + (lane & 15);
        b_row_off[nf] = rowB * 128;
        br7[nf] = rowB & 7;
    }
    const int cc = (lane & 3) * 2;

    int stage = 0;
    for (int siter = 0; siter < NSLICES; siter++) {
        const int nt = siter >> 2, ks = siter & 3;

        if (siter < NSLICES - 2) cp_wait<1>(); else cp_wait<0>();
        __syncthreads();

        const int nsi = siter + 2;
        if (nsi < NSLICES) {
            int pst = stage + 2; if (pst >= 3) pst -= 3;
            const int nnt = nsi >> 2, nks = nsi & 3;
            const char* bsrc = Bbase + (size_t)(nnt * 128 + brow) * 512 + nks * 128 + bhalf * 64;
            const uint32_t bdst = sb + APLANE + pst * BTILE + brow * 128;
            #pragma unroll
            for (int j = 0; j < 4; j++) {
                const int c16 = bhalf * 4 + j;
                cp16(bdst + ((c16 ^ br7l) << 4), bsrc + j * 16);
            }
            cp_commit();
        }

        const uint32_t sbB = sb + APLANE + stage * BTILE;
        #pragma unroll
        for (int kk = 0; kk < 4; kk++) {
            uint32_t a[2][4], b[4][4];
            const int c16a = kk * 2 + chi;
            #pragma unroll
            for (int mi = 0; mi < 2; mi++)
                LDSM4(a[mi], a_row_sm[mi] + ks * 128 + ((c16a ^ ar7[mi]) << 4));
            #pragma unroll
            for (int nf = 0; nf < 4; nf++)
                LDSM4(b[nf], sbB + b_row_off[nf] + ((c16a ^ br7[nf]) << 4));
            #pragma unroll
            for (int mi = 0; mi < 2; mi++)
                #pragma unroll
                for (int nf = 0; nf < 4; nf++) {
                    MMA16816(acc[mi][nf * 2 + 0], a[mi], b[nf][0], b[nf][2]);
                    MMA16816(acc[mi][nf * 2 + 1], a[mi], b[nf][1], b[nf][3]);
                }
        }
        if (++stage == 3) stage = 0;

        if (ks == 3) {
            const int nbase = ngrp * 512 + nt * 128 + wn * 64;
            #pragma unroll
            for (int ni = 0; ni < 8; ni++) {
                #pragma unroll
                for (int c = 0; c < 2; c++) {
                    const int n = nbase + ni * 8 + cc + c;
                    const float hn = __ldg(&g_hn[n]);
                    const ull lowkey = (ull)(NE - 1 - n);
                    #pragma unroll
                    for (int mi = 0; mi < 2; mi++)
                        #pragma unroll
                        for (int h = 0; h < 2; h++) {
                            const float sc = acc[mi][ni][h * 2 + c] - hn;
                            const ull key = ((ull)mono_f32(sc) << 32) | lowkey;
                            if (key > k1[mi][h]) { k2[mi][h] = k1[mi][h]; k1[mi][h] = key; }
                            else if (key > k2[mi][h]) { k2[mi][h] = key; }
                            acc[mi][ni][h * 2 + c] = 0.f;
                        }
                }
            }
        }
    }

    #pragma unroll
    for (int mi = 0; mi < 2; mi++)
        #pragma unroll
        for (int h = 0; h < 2; h++) {
            ull a1 = k1[mi][h], a2 = k2[mi][h];
            #pragma unroll
            for (int off = 1; off <= 2; off <<= 1) {
                ull o1 = __shfl_xor_sync(0xffffffffu, a1, off);
                ull o2 = __shfl_xor_sync(0xffffffffu, a2, off);
                ull n1 = umax64(a1, o1);
                ull n2 = umax64(umin64(a1, o1), umax64(a2, o2));
                a1 = n1; a2 = n2;
            }
            if ((lane & 3) == 0) {
                const int token = mtile * 128 + wm * 32 + mi * 16 + h * 8 + (lane >> 2);
                ull* dst = g_top + (size_t)token * 128 + ngrp * 4 + wn * 2;
                dst[0] = a1;
                dst[1] = a2;
            }
        }
}

// ================= fixup: global top-4 + exact fp32 rescore =================
__global__ void fixup_kernel(const float* __restrict__ cb) {
    const int token = blockIdx.x * 8 + (threadIdx.x >> 5);
    const int lane = threadIdx.x & 31;

    const ull* tp = g_top + (size_t)token * 128;
    ull k[4];
    #pragma unroll
    for (int i = 0; i < 4; i++) k[i] = tp[lane + 32 * i];

    int cand[4];
    #pragma unroll
    for (int r = 0; r < 4; r++) {
        ull m = 0;
        #pragma unroll
        for (int i = 0; i < 4; i++) m = umax64(m, k[i]);
        #pragma unroll
        for (int off = 16; off; off >>= 1)
            m = umax64(m, __shfl_xor_sync(0xffffffffu, m, off));
        #pragma unroll
        for (int i = 0; i < 4; i++) if (k[i] == m) k[i] = 0;
        cand[r] = (NE - 1) - (int)(m & 0xFFFFFFFFull);
    }

    float zv[8];
    #pragma unroll
    for (int i = 0; i < 8; i++)
        zv[i] = g_zt[(size_t)token * CD + lane + 32 * i];

    ull bestk = 0;
    #pragma unroll
    for (int r = 0; r < 4; r++) {
        const int n = cand[r];
        const float* crow = cb + (size_t)n * CD;
        float s = 0.f;
        #pragma unroll
        for (int i = 0; i < 8; i++) s = fmaf(zv[i], __ldg(&crow[lane + 32 * i]), s);
        #pragma unroll
        for (int off = 16; off; off >>= 1) s += __shfl_xor_sync(0xffffffffu, s, off);
        s -= g_hn[n];
        const ull key = ((ull)mono_f32(s) << 32) | (ull)(NE - 1 - n);
        bestk = umax64(bestk, key);
    }
    if (lane == 0) g_best[token] = (NE - 1) - (int)(bestk & 0xFFFFFFFFull);
}

// ================= gather z_q (smem transpose) + spherical distance =================
#define GT_BLKS (NTOK / 32)   // 128
#define SPH_BLKS ((EMB * 8) / 256)  // 16: 512 e x 8 cut-groups
__global__ void gather_sph_kernel(const float* __restrict__ cb, const float* __restrict__ ie,
                                  const float* __restrict__ pr, float* __restrict__ out) {
    if (blockIdx.x < GT_BLKS) {
        extern __shared__ float ts[];       // [32 tokens][257]
        const int tid = threadIdx.x;
        // phase 1: coalesced codebook row loads -> staged transpose
        const int r = tid >> 3, part = tid & 7;   // 32 rows x 8 threads
        const int n = g_best[blockIdx.x * 32 + r];
        const float* crow = cb + (size_t)n * CD;
        float* dst = ts + r * 257;
        #pragma unroll
        for (int j = 0; j < 8; j++) {
            const int c = part * 4 + j * 32;      // conflict-free float4 stores
            float4 v = *(const float4*)(crow + c);
            dst[c + 0] = v.x; dst[c + 1] = v.y; dst[c + 2] = v.z; dst[c + 3] = v.w;
        }
        __syncthreads();
        // phase 2: coalesced stores to [B,C,H,W]
        const int w = tid >> 5, l = tid & 31;
        const int t0 = blockIdx.x * 32;
        const int bb = t0 >> 10, p0 = t0 & 1023;
        float* ob = out + (size_t)bb * CD * HW + p0;
        #pragma unroll
        for (int i = 0; i < 32; i++) {
            const int c = w + 8 * i;
            ob[(size_t)c * HW + l] = ts[l * 257 + c];
        }
        return;
    }
    // sph: 4096 threads = 512 e x 8 cut-groups of 4; reduce within 8-lane groups
    const int idx = (blockIdx.x - GT_BLKS) * 256 + threadIdx.x;
    const int e = idx >> 3, jg = idx & 7;
    float pv[BATCH];
    float pn = 0.f;
    #pragma unroll
    for (int b = 0; b < BATCH; b++) { pv[b] = pr[b * EMB + e]; pn += pv[b] * pv[b]; }
    pn = fmaxf(sqrtf(pn), 1e-12f);
    #pragma unroll
    for (int b = 0; b < BATCH; b++) pv[b] /= pn;
    float acc = 0.f;
    #pragma unroll
    for (int jj = 0; jj < 4; jj++) {
        const int j = jg * 4 + jj;
        float q[BATCH];
        float qn = 0.f;
        #pragma unroll
        for (int b = 0; b < BATCH; b++) {
            q[b] = ie[(size_t)(j * BATCH + b) * EMB + e];
            qn += q[b] * q[b];
        }
        qn = fmaxf(sqrtf(qn), 1e-12f);
        float d2 = 0.f;
        #pragma unroll
        for (int b = 0; b < BATCH; b++) {
            float df = q[b] / qn - pv[b];
            d2 += df * df;
        }
        float h = fminf(0.5f * sqrtf(d2), 1.0f);
        float a = asinf(h);
        acc += 2.0f * a * a;
    }
    #pragma unroll
    for (int off = 1; off <= 4; off <<= 1)
        acc += __shfl_xor_sync(0xffffffffu, acc, off);
    if (jg == 0) out[ZQ_N + e] = acc * (1.0f / NCUTS);
}

#define GT_SMEM (32 * 257 * 4)

// ================= launch =================
extern "C" void kernel_launch(void* const* d_in, const int* in_sizes, int n_in,
                              void* d_out, int out_size) {
    const float* z  = (const float*)d_in[0];
    const float* cb = (const float*)d_in[1];
    const float* ie = (const float*)d_in[2];
    const float* pr = (const float*)d_in[3];
    float* out = (float*)d_out;

    cudaFuncSetAttribute(vq_gemm, cudaFuncAttributeMaxDynamicSharedMemorySize, SMEM_B);
    cudaFuncSetAttribute(gather_sph_kernel, cudaFuncAttributeMaxDynamicSharedMemorySize, GT_SMEM);

    convAB_kernel<<<A_BLKS + B_BLKS, 256>>>(z, cb);
    vq_gemm<<<dim3(NE / 512, NTOK / 128), 256, SMEM_B>>>();
    fixup_kernel<<<NTOK / 8, 256>>>(cb);
    gather_sph_kernel<<<GT_BLKS + SPH_BLKS, 256, GT_SMEM>>>(cb, ie, pr, out);
}